// round 14
// baseline (speedup 1.0000x reference)
#include <cuda_runtime.h>
#include <cuda_fp16.h>
#include <cstdint>

#define HW   3136
#define HWP  3200
#define WDIM 56
#define CIN  240
#define MID  120
#define COUT 480
#define NB   32

// ---------------------------------------------------------------------------
// Scratch (device globals are zero-initialized; pad regions never written)
// ---------------------------------------------------------------------------
__device__ __half g_y1h[NB * MID * HW];            // conv1+bn1+relu (half)
__device__ __half g_th[(size_t)NB * 128 * HWP];    // dw+bn2 shuffled, half, ch pad 128
__device__ __half g_xh[(size_t)NB * 256 * HWP];    // x as half, ch pad 256
// fp16 weight fragments in mma.m16n8k16 lane order:
__device__ __half g_fA[4 * 8  * 8 * 32 * 8];       // conv3 dense, scale3 folded, K=128 pad
__device__ __half g_fB[4 * 16 * 8 * 32 * 8];       // wsc, scale_sc folded, K=256 pad
__device__ __half g_f1[16 * 8 * 32 * 8];           // w1 block-diag, scale1 folded, 128x256

__device__ __forceinline__ void mma16h(float* d, const uint4& a, uint32_t b0, uint32_t b1) {
    asm volatile(
        "mma.sync.aligned.m16n8k16.row.col.f32.f16.f16.f32 "
        "{%0,%1,%2,%3}, {%4,%5,%6,%7}, {%8,%9}, {%0,%1,%2,%3};"
        : "+f"(d[0]), "+f"(d[1]), "+f"(d[2]), "+f"(d[3])
        : "r"(a.x), "r"(a.y), "r"(a.z), "r"(a.w), "r"(b0), "r"(b1));
}
__device__ __forceinline__ uint32_t smem_u32(const void* p) {
    uint32_t a;
    asm("{ .reg .u64 t; cvta.to.shared.u64 t, %1; cvt.u32.u64 %0, t; }" : "=r"(a) : "l"(p));
    return a;
}
__device__ __forceinline__ void pref_l1(const void* p) {
    asm volatile("prefetch.global.L1 [%0];" :: "l"(p));
}

// ---------------------------------------------------------------------------
// K0 (merged): weight fold/pack (blocks [0, NFB)) + x fp32->fp16 (rest)
// ---------------------------------------------------------------------------
#define NFB 896    // (65536 + 131072 + 32768) / 256

__global__ void k_prep(const float* __restrict__ w3, const float* __restrict__ s3,
                       const float* __restrict__ wsc, const float* __restrict__ ssc,
                       const float* __restrict__ w1, const float* __restrict__ s1,
                       const float* __restrict__ x) {
    int bi = blockIdx.x;
    if (bi < NFB) {
        int i = bi * 256 + threadIdx.x;
        const int NA = 4 * 8 * 8 * 32 * 8;        // 65536
        const int NBW = 4 * 16 * 8 * 32 * 8;      // 131072
        const int NC = 16 * 8 * 32 * 8;           // 32768
        if (i < NA) {
            int e = i & 1, q = (i >> 1) & 3, lane = (i >> 3) & 31;
            int t = (i >> 8) & 7, c = (i >> 11) & 7, mt = i >> 14;
            int row = mt * 128 + t * 16 + (lane >> 2) + (q & 1) * 8;
            int k   = c * 16 + (lane & 3) * 2 + e + (q >> 1) * 8;
            float v = 0.f;
            if (row < COUT && k < MID) {
                int g = row / 160, lk = k - g * 40;
                if (lk >= 0 && lk < 40) v = w3[row * 40 + lk] * s3[row];
            }
            g_fA[i] = __float2half(v);
        } else if (i < NA + NBW) {
            int j = i - NA;
            int e = j & 1, q = (j >> 1) & 3, lane = (j >> 3) & 31;
            int t = (j >> 8) & 7;
            int rest = j >> 11;
            int c = rest & 15, mt = rest >> 4;
            int row = mt * 128 + t * 16 + (lane >> 2) + (q & 1) * 8;
            int k   = c * 16 + (lane & 3) * 2 + e + (q >> 1) * 8;
            float v = (row < COUT && k < CIN) ? wsc[row * CIN + k] * ssc[row] : 0.f;
            g_fB[j] = __float2half(v);
        } else {
            int l = i - NA - NBW;
            if (l < NC) {
                int e = l & 1, q = (l >> 1) & 3, lane = (l >> 3) & 31;
                int t = (l >> 8) & 7, c = l >> 11;
                int row = t * 16 + (lane >> 2) + (q & 1) * 8;
                int k   = c * 16 + (lane & 3) * 2 + e + (q >> 1) * 8;
                float v = 0.f;
                if (row < MID) {
                    int g = row / 40, lk = k - g * 80;
                    if (lk >= 0 && lk < 80) v = w1[row * 80 + lk] * s1[row];
                }
                g_f1[l] = __float2half(v);
            }
        }
    } else {
        int idx = (bi - NFB) * 256 + threadIdx.x;
        const int Q = HW / 4;                      // 784
        if (idx >= NB * CIN * Q) return;
        int row = idx / Q, p4 = idx - row * Q;
        int n = row / CIN, c = row - n * CIN;
        float4 v = *(const float4*)(x + (size_t)row * HW + p4 * 4);
        __half2 h[2];
        h[0] = __floats2half2_rn(v.x, v.y);
        h[1] = __floats2half2_rn(v.z, v.w);
        *(uint2*)(g_xh + ((size_t)n * 256 + c) * HWP + p4 * 4) = *(const uint2*)h;
    }
}

// ---------------------------------------------------------------------------
// K1 (tensor): grouped 1x1 conv + BN + ReLU via fp16 mma -> g_y1h
// ---------------------------------------------------------------------------
#define STAGES 4

__global__ __launch_bounds__(256)
void k_conv1_t(const float* __restrict__ sh1) {
    extern __shared__ __align__(16) char BsRaw[];
    uint32_t sbB = smem_u32(BsRaw);

    int tid = threadIdx.x;
    int wid = tid >> 5, lane = tid & 31;
    int nb = (wid & 1) * 64;
    int nbc = (wid & 1) * 8;
    int wt = (wid >> 1) * 2;

    int p0  = blockIdx.x * 128;
    int img = blockIdx.y;

    const int klo = (wt < 4) ? 0 : (wt == 4) ? 80 : 160;
    const int khi = (wt == 0) ? 80 : (wt == 2) ? 160 : 240;

    const __half* srcB = g_xh + (size_t)img * 256 * HWP;

    float acc[2][8][4];
#pragma unroll
    for (int t = 0; t < 2; t++)
#pragma unroll
        for (int j = 0; j < 8; j++)
#pragma unroll
            for (int q = 0; q < 4; q++) acc[t][j][q] = 0.f;

    float sh1v[2][2];
#pragma unroll
    for (int t = 0; t < 2; t++)
#pragma unroll
        for (int h = 0; h < 2; h++) {
            int co = wt * 16 + t * 16 + (lane >> 2) + h * 8;
            sh1v[t][h] = (co < MID) ? sh1[co] : 0.f;
        }

    int lk = tid >> 4, lc = tid & 15;

    auto issue = [&](int s) {
        uint32_t db = sbB + (s & (STAGES - 1)) * 16384;
#pragma unroll
        for (int it = 0; it < 4; it++) {
            int k = lk + it * 16;
            const __half* gp = srcB + (size_t)(s * 64 + k) * HWP + p0 + lc * 8;
            uint32_t dst = db + k * 256 + ((lc ^ (k & 7)) << 4);
            asm volatile("cp.async.cg.shared.global [%0], [%1], 16;"
                         :: "r"(dst), "l"(gp));
        }
        asm volatile("cp.async.commit_group;");
    };

    issue(0); issue(1); issue(2);

    const int rowl = ((lane >> 3) & 1) * 8 + (lane & 7);
    const int csel = lane >> 4;

    for (int c = 0; c < 4; c++) {
        if (c < 2)       asm volatile("cp.async.wait_group 2;");
        else if (c == 2) asm volatile("cp.async.wait_group 1;");
        else             asm volatile("cp.async.wait_group 0;");
        __syncthreads();

        bool active = (c * 64 < khi) && (c * 64 + 64 > klo);
        if (active) {
            uint32_t stageb = sbB + (c & (STAGES - 1)) * 16384;
#pragma unroll
            for (int h = 0; h < 2; h++) {
                int c32 = c * 2 + h;
                const __half* fb = g_f1 + ((size_t)((c32 * 2) * 8 + wt) * 32 + lane) * 8;
                uint4 af[2][2];
#pragma unroll
                for (int g = 0; g < 2; g++)
#pragma unroll
                    for (int t = 0; t < 2; t++)
                        af[g][t] = *(const uint4*)(fb + ((size_t)g * 8 + t) * 32 * 8);

                uint32_t base = stageb + h * 8192;
#pragma unroll
                for (int g = 0; g < 2; g++) {
                    int row = g * 16 + rowl;
#pragma unroll
                    for (int jp = 0; jp < 4; jp++) {
                        int c16 = nbc + jp * 2 + csel;
                        uint32_t addr = base + row * 256 + ((c16 ^ (row & 7)) << 4);
                        uint32_t b0, b1, b2, b3;
                        asm volatile(
                            "ldmatrix.sync.aligned.m8n8.x4.trans.shared.b16 {%0,%1,%2,%3}, [%4];"
                            : "=r"(b0), "=r"(b1), "=r"(b2), "=r"(b3) : "r"(addr));
                        mma16h(acc[0][jp * 2],     af[g][0], b0, b1);
                        mma16h(acc[1][jp * 2],     af[g][1], b0, b1);
                        mma16h(acc[0][jp * 2 + 1], af[g][0], b2, b3);
                        mma16h(acc[1][jp * 2 + 1], af[g][1], b2, b3);
                    }
                }
            }
        }
        if (c + STAGES - 1 < 4) issue(c + STAGES - 1);
    }

    // epilogue: relu(acc + shift1) -> g_y1h (half2 stores)
#pragma unroll
    for (int t = 0; t < 2; t++) {
#pragma unroll
        for (int h = 0; h < 2; h++) {
            int co = wt * 16 + t * 16 + (lane >> 2) + h * 8;
            if (co >= MID) continue;
            __half* orow = g_y1h + ((size_t)img * MID + co) * HW;
            float bv = sh1v[t][h];
#pragma unroll
            for (int j = 0; j < 8; j++) {
                int p = p0 + nb + j * 8 + 2 * (lane & 3);
                if (p < HW) {
                    *(__half2*)(orow + p) = __floats2half2_rn(
                        fmaxf(acc[t][j][h * 2 + 0] + bv, 0.f),
                        fmaxf(acc[t][j][h * 2 + 1] + bv, 0.f));
                }
            }
        }
    }
}

// ---------------------------------------------------------------------------
// K2: depthwise 3x3 + BN2 + channel shuffle: g_y1h -> g_th (half)
// ---------------------------------------------------------------------------
__global__ __launch_bounds__(448)
void k_dw(const float* __restrict__ w2, const float* __restrict__ s2,
          const float* __restrict__ b2) {
    __shared__ float tile[58][72];
    int m = blockIdx.x;
    int n = blockIdx.y;
    int tx = threadIdx.x, ty = threadIdx.y;
    int tid = ty * 56 + tx;

    if (tid < 36) {
        int r = (tid < 18) ? 0 : 57;
        int c4 = (tid % 18) * 4;
        *(float4*)&tile[r][c4] = make_float4(0.f, 0.f, 0.f, 0.f);
    } else if (tid < 36 + 112) {
        int t = tid - 36;
        int r = 1 + (t >> 1);
        tile[r][(t & 1) ? 64 : 7] = 0.f;
    }

    const __half* src = g_y1h + ((size_t)n * MID + m) * HW;
    if (tid < 392) {
        int r = tid / 7, q = tid - r * 7;
        uint4 v = *(const uint4*)(src + r * 56 + q * 8);
        const __half2* hp = (const __half2*)&v;
        float2 f0 = __half22float2(hp[0]);
        float2 f1 = __half22float2(hp[1]);
        float2 f2 = __half22float2(hp[2]);
        float2 f3 = __half22float2(hp[3]);
        float* d = &tile[r + 1][8 + q * 8];
        *(float4*)d       = make_float4(f0.x, f0.y, f1.x, f1.y);
        *(float4*)(d + 4) = make_float4(f2.x, f2.y, f3.x, f3.y);
    }
    __syncthreads();

    float wv[9];
#pragma unroll
    for (int q = 0; q < 9; q++) wv[q] = __ldg(&w2[m * 9 + q]);
    float sc = __ldg(&s2[m]), sh = __ldg(&b2[m]);

    int cs = (m % 40) * 3 + m / 40;
    __half* dst = g_th + ((size_t)n * 128 + cs) * HWP;

    int r0 = ty * 7;
    int cx = tx + 7;
    float a0 = tile[r0][cx],     a1 = tile[r0][cx + 1],     a2 = tile[r0][cx + 2];
    float e0 = tile[r0 + 1][cx], e1 = tile[r0 + 1][cx + 1], e2 = tile[r0 + 1][cx + 2];
#pragma unroll
    for (int i = 0; i < 7; i++) {
        int row = r0 + i;
        float c0 = tile[row + 2][cx], c1 = tile[row + 2][cx + 1], c2 = tile[row + 2][cx + 2];
        float sum = wv[0] * a0;
        sum = fmaf(wv[1], a1, sum); sum = fmaf(wv[2], a2, sum);
        sum = fmaf(wv[3], e0, sum); sum = fmaf(wv[4], e1, sum);
        sum = fmaf(wv[5], e2, sum); sum = fmaf(wv[6], c0, sum);
        sum = fmaf(wv[7], c1, sum); sum = fmaf(wv[8], c2, sum);
        dst[row * WDIM + tx] = __float2half(fmaf(sc, sum, sh));
        a0 = e0; a1 = e1; a2 = e2;
        e0 = c0; e1 = c1; e2 = c2;
    }
}

// ---------------------------------------------------------------------------
// K3: fused conv3 + relu(bn3) + shortcut + add, with L1 prefetch of next
// chunk's A fragments (removes per-chunk L2-latency bubble on af loads).
// ---------------------------------------------------------------------------
__global__ __launch_bounds__(256)
void k_main_m(const float* __restrict__ sh3, const float* __restrict__ shsc,
              float* __restrict__ out) {
    extern __shared__ __align__(16) char BsRaw[];
    uint32_t sbB = smem_u32(BsRaw);

    int tid = threadIdx.x;
    int wid = tid >> 5, lane = tid & 31;
    int nb = (wid & 1) * 64;
    int nbc = (wid & 1) * 8;
    int wt = (wid >> 1) * 2;

    int mt  = blockIdx.x;
    int p0  = blockIdx.y * 128;
    int img = blockIdx.z;
    int rbase = mt * 128 + wt * 16;

    const int sA = (mt == 3) ? 1 : 0;
    const int nA = (mt == 1 || mt == 2) ? 2 : 1;
    const int nchunk = nA + 4;

    const __half* srcA = g_th + (size_t)img * 128 * HWP;
    const __half* srcB = g_xh + (size_t)img * 256 * HWP;

    float acc[2][8][4];
#pragma unroll
    for (int t = 0; t < 2; t++)
#pragma unroll
        for (int j = 0; j < 8; j++)
#pragma unroll
            for (int q = 0; q < 4; q++) acc[t][j][q] = 0.f;

    float v3[2][2], vsc[2][2];
#pragma unroll
    for (int t = 0; t < 2; t++)
#pragma unroll
        for (int h = 0; h < 2; h++) {
            int co = rbase + t * 16 + (lane >> 2) + h * 8;
            bool ok = co < COUT;
            v3[t][h]  = ok ? sh3[co]  : 0.f;
            vsc[t][h] = ok ? shsc[co] : 0.f;
        }

    int lk = tid >> 4, lc = tid & 15;

    auto issue = [&](int s) {
        const __half* src; int kbase;
        if (s < nA) { src = srcA; kbase = (sA + s) * 64; }
        else        { src = srcB; kbase = (s - nA) * 64; }
        uint32_t db = sbB + (s & (STAGES - 1)) * 16384;
#pragma unroll
        for (int it = 0; it < 4; it++) {
            int k = lk + it * 16;
            const __half* gp = src + (size_t)(kbase + k) * HWP + p0 + lc * 8;
            uint32_t dst = db + k * 256 + ((lc ^ (k & 7)) << 4);
            asm volatile("cp.async.cg.shared.global [%0], [%1], 16;"
                         :: "r"(dst), "l"(gp));
        }
        asm volatile("cp.async.commit_group;");
    };

    // A-fragment base for chunk cc, half h
    auto af_base = [&](int cc, int h) -> const __half* {
        int c32 = (cc < nA) ? (sA + cc) * 2 + h : (cc - nA) * 2 + h;
        return (cc < nA)
            ? g_fA + ((size_t)((mt * 8  + c32 * 2) * 8 + wt) * 32 + lane) * 8
            : g_fB + ((size_t)((mt * 16 + c32 * 2) * 8 + wt) * 32 + lane) * 8;
    };

    issue(0); issue(1); issue(2);

    // prefetch chunk 0's A fragments
#pragma unroll
    for (int h = 0; h < 2; h++) {
        const __half* fbp = af_base(0, h);
#pragma unroll
        for (int g = 0; g < 2; g++)
#pragma unroll
            for (int t = 0; t < 2; t++)
                pref_l1(fbp + ((size_t)g * 8 + t) * 32 * 8);
    }

    const int rowl = ((lane >> 3) & 1) * 8 + (lane & 7);
    const int csel = lane >> 4;

    for (int c = 0; c < nchunk; c++) {
        if (c < nchunk - 2)       asm volatile("cp.async.wait_group 2;");
        else if (c == nchunk - 2) asm volatile("cp.async.wait_group 1;");
        else                      asm volatile("cp.async.wait_group 0;");
        __syncthreads();

        // prefetch next chunk's A fragments into L1 (hidden under compute)
        if (c + 1 < nchunk) {
#pragma unroll
            for (int h = 0; h < 2; h++) {
                const __half* fbp = af_base(c + 1, h);
#pragma unroll
                for (int g = 0; g < 2; g++)
#pragma unroll
                    for (int t = 0; t < 2; t++)
                        pref_l1(fbp + ((size_t)g * 8 + t) * 32 * 8);
            }
        }

        uint32_t stageb = sbB + (c & (STAGES - 1)) * 16384;

#pragma unroll
        for (int h = 0; h < 2; h++) {
            const __half* fb = af_base(c, h);
            uint4 af[2][2];
#pragma unroll
            for (int g = 0; g < 2; g++)
#pragma unroll
                for (int t = 0; t < 2; t++)
                    af[g][t] = *(const uint4*)(fb + ((size_t)g * 8 + t) * 32 * 8);

            uint32_t base = stageb + h * 8192;
#pragma unroll
            for (int g = 0; g < 2; g++) {
                int row = g * 16 + rowl;
#pragma unroll
                for (int jp = 0; jp < 4; jp++) {
                    int c16 = nbc + jp * 2 + csel;
                    uint32_t addr = base + row * 256 + ((c16 ^ (row & 7)) << 4);
                    uint32_t b0, b1, b2, b3;
                    asm volatile(
                        "ldmatrix.sync.aligned.m8n8.x4.trans.shared.b16 {%0,%1,%2,%3}, [%4];"
                        : "=r"(b0), "=r"(b1), "=r"(b2), "=r"(b3) : "r"(addr));
                    mma16h(acc[0][jp * 2],     af[g][0], b0, b1);
                    mma16h(acc[1][jp * 2],     af[g][1], b0, b1);
                    mma16h(acc[0][jp * 2 + 1], af[g][0], b2, b3);
                    mma16h(acc[1][jp * 2 + 1], af[g][1], b2, b3);
                }
            }
        }

        if (c == nA - 1) {
#pragma unroll
            for (int t = 0; t < 2; t++)
#pragma unroll
                for (int j = 0; j < 8; j++)
#pragma unroll
                    for (int q = 0; q < 4; q++)
                        acc[t][j][q] = fmaxf(acc[t][j][q] + v3[t][q >> 1], 0.f);
        }

        if (c + STAGES - 1 < nchunk) issue(c + STAGES - 1);
    }

#pragma unroll
    for (int t = 0; t < 2; t++) {
#pragma unroll
        for (int h = 0; h < 2; h++) {
            int co = rbase + t * 16 + (lane >> 2) + h * 8;
            if (co >= COUT) continue;
            float* orow = out + ((size_t)img * COUT + co) * HW;
            float bv = vsc[t][h];
#pragma unroll
            for (int j = 0; j < 8; j++) {
                int p = p0 + nb + j * 8 + 2 * (lane & 3);
                if (p < HW) {
                    float2 v;
                    v.x = acc[t][j][h * 2 + 0] + bv;
                    v.y = acc[t][j][h * 2 + 1] + bv;
                    *(float2*)(orow + p) = v;
                }
            }
        }
    }
}

// ---------------------------------------------------------------------------
extern "C" void kernel_launch(void* const* d_in, const int* in_sizes, int n_in,
                              void* d_out, int out_size) {
    const float* x   = (const float*)d_in[0];
    const float* w1  = (const float*)d_in[1];
    const float* s1  = (const float*)d_in[2];
    const float* b1  = (const float*)d_in[3];
    const float* w2  = (const float*)d_in[4];
    const float* s2  = (const float*)d_in[5];
    const float* b2  = (const float*)d_in[6];
    const float* w3  = (const float*)d_in[7];
    const float* s3  = (const float*)d_in[8];
    const float* b3  = (const float*)d_in[9];
    const float* wsc = (const float*)d_in[10];
    const float* ssc = (const float*)d_in[11];
    const float* bsc = (const float*)d_in[12];
    float* out = (float*)d_out;

    static int smem_set = 0;
    if (!smem_set) {
        cudaFuncSetAttribute(k_main_m, cudaFuncAttributeMaxDynamicSharedMemorySize,
                             STAGES * 16384);
        cudaFuncSetAttribute(k_conv1_t, cudaFuncAttributeMaxDynamicSharedMemorySize,
                             STAGES * 16384);
        smem_set = 1;
    }

    int ncvt_blocks = (NB * CIN * (HW / 4) + 255) / 256;   // 23520
    k_prep<<<NFB + ncvt_blocks, 256>>>(w3, s3, wsc, ssc, w1, s1, x);
    k_conv1_t<<<dim3(25, NB), 256, STAGES * 16384>>>(b1);
    k_dw<<<dim3(MID, NB), dim3(56, 8)>>>(w2, s2, b2);
    k_main_m<<<dim3(4, 25, NB), 256, STAGES * 16384>>>(b3, bsc, out);
}

// round 15
// speedup vs baseline: 1.0495x; 1.0495x over previous
#include <cuda_runtime.h>
#include <cuda_fp16.h>
#include <cstdint>

#define HW   3136
#define HWP  3200
#define WDIM 56
#define CIN  240
#define MID  120
#define COUT 480
#define NB   32

// ---------------------------------------------------------------------------
// Scratch (device globals are zero-initialized; pad regions never written)
// ---------------------------------------------------------------------------
__device__ __half g_y1h[NB * MID * HW];            // conv1+bn1+relu (half)
__device__ __half g_th[(size_t)NB * 128 * HWP];    // dw+bn2 shuffled, half, ch pad 128
__device__ __half g_xh[(size_t)NB * 256 * HWP];    // x as half, ch pad 256
// fp16 weight fragments in mma.m16n8k16 lane order:
__device__ __half g_fA[4 * 8  * 8 * 32 * 8];       // conv3 dense, scale3 folded, K=128 pad
__device__ __half g_fB[4 * 16 * 8 * 32 * 8];       // wsc, scale_sc folded, K=256 pad
__device__ __half g_f1[16 * 8 * 32 * 8];           // w1 block-diag, scale1 folded, 128x256

__device__ __forceinline__ void mma16h(float* d, const uint4& a, uint32_t b0, uint32_t b1) {
    asm volatile(
        "mma.sync.aligned.m16n8k16.row.col.f32.f16.f16.f32 "
        "{%0,%1,%2,%3}, {%4,%5,%6,%7}, {%8,%9}, {%0,%1,%2,%3};"
        : "+f"(d[0]), "+f"(d[1]), "+f"(d[2]), "+f"(d[3])
        : "r"(a.x), "r"(a.y), "r"(a.z), "r"(a.w), "r"(b0), "r"(b1));
}
__device__ __forceinline__ uint32_t smem_u32(const void* p) {
    uint32_t a;
    asm("{ .reg .u64 t; cvta.to.shared.u64 t, %1; cvt.u32.u64 %0, t; }" : "=r"(a) : "l"(p));
    return a;
}
__device__ __forceinline__ void st_cs_f2(float* p, float x, float y) {
    asm volatile("st.global.cs.v2.f32 [%0], {%1, %2};" :: "l"(p), "f"(x), "f"(y) : "memory");
}

// ---------------------------------------------------------------------------
// K0 (merged): weight fold/pack (blocks [0, NFB)) + x fp32->fp16 (rest)
// ---------------------------------------------------------------------------
#define NFB 896    // (65536 + 131072 + 32768) / 256

__global__ void k_prep(const float* __restrict__ w3, const float* __restrict__ s3,
                       const float* __restrict__ wsc, const float* __restrict__ ssc,
                       const float* __restrict__ w1, const float* __restrict__ s1,
                       const float* __restrict__ x) {
    int bi = blockIdx.x;
    if (bi < NFB) {
        int i = bi * 256 + threadIdx.x;
        const int NA = 4 * 8 * 8 * 32 * 8;        // 65536
        const int NBW = 4 * 16 * 8 * 32 * 8;      // 131072
        const int NC = 16 * 8 * 32 * 8;           // 32768
        if (i < NA) {
            int e = i & 1, q = (i >> 1) & 3, lane = (i >> 3) & 31;
            int t = (i >> 8) & 7, c = (i >> 11) & 7, mt = i >> 14;
            int row = mt * 128 + t * 16 + (lane >> 2) + (q & 1) * 8;
            int k   = c * 16 + (lane & 3) * 2 + e + (q >> 1) * 8;
            float v = 0.f;
            if (row < COUT && k < MID) {
                int g = row / 160, lk = k - g * 40;
                if (lk >= 0 && lk < 40) v = w3[row * 40 + lk] * s3[row];
            }
            g_fA[i] = __float2half(v);
        } else if (i < NA + NBW) {
            int j = i - NA;
            int e = j & 1, q = (j >> 1) & 3, lane = (j >> 3) & 31;
            int t = (j >> 8) & 7;
            int rest = j >> 11;
            int c = rest & 15, mt = rest >> 4;
            int row = mt * 128 + t * 16 + (lane >> 2) + (q & 1) * 8;
            int k   = c * 16 + (lane & 3) * 2 + e + (q >> 1) * 8;
            float v = (row < COUT && k < CIN) ? wsc[row * CIN + k] * ssc[row] : 0.f;
            g_fB[j] = __float2half(v);
        } else {
            int l = i - NA - NBW;
            if (l < NC) {
                int e = l & 1, q = (l >> 1) & 3, lane = (l >> 3) & 31;
                int t = (l >> 8) & 7, c = l >> 11;
                int row = t * 16 + (lane >> 2) + (q & 1) * 8;
                int k   = c * 16 + (lane & 3) * 2 + e + (q >> 1) * 8;
                float v = 0.f;
                if (row < MID) {
                    int g = row / 40, lk = k - g * 80;
                    if (lk >= 0 && lk < 80) v = w1[row * 80 + lk] * s1[row];
                }
                g_f1[l] = __float2half(v);
            }
        }
    } else {
        int idx = (bi - NFB) * 256 + threadIdx.x;
        const int Q = HW / 4;                      // 784
        if (idx >= NB * CIN * Q) return;
        int row = idx / Q, p4 = idx - row * Q;
        int n = row / CIN, c = row - n * CIN;
        float4 v = *(const float4*)(x + (size_t)row * HW + p4 * 4);
        __half2 h[2];
        h[0] = __floats2half2_rn(v.x, v.y);
        h[1] = __floats2half2_rn(v.z, v.w);
        *(uint2*)(g_xh + ((size_t)n * 256 + c) * HWP + p4 * 4) = *(const uint2*)h;
    }
}

// ---------------------------------------------------------------------------
// K1 (tensor): grouped 1x1 conv + BN + ReLU via fp16 mma -> g_y1h
// ---------------------------------------------------------------------------
#define STAGES 4

__global__ __launch_bounds__(256)
void k_conv1_t(const float* __restrict__ sh1) {
    extern __shared__ __align__(16) char BsRaw[];
    uint32_t sbB = smem_u32(BsRaw);

    int tid = threadIdx.x;
    int wid = tid >> 5, lane = tid & 31;
    int nb = (wid & 1) * 64;
    int nbc = (wid & 1) * 8;
    int wt = (wid >> 1) * 2;

    int p0  = blockIdx.x * 128;
    int img = blockIdx.y;

    const int klo = (wt < 4) ? 0 : (wt == 4) ? 80 : 160;
    const int khi = (wt == 0) ? 80 : (wt == 2) ? 160 : 240;

    const __half* srcB = g_xh + (size_t)img * 256 * HWP;

    float acc[2][8][4];
#pragma unroll
    for (int t = 0; t < 2; t++)
#pragma unroll
        for (int j = 0; j < 8; j++)
#pragma unroll
            for (int q = 0; q < 4; q++) acc[t][j][q] = 0.f;

    float sh1v[2][2];
#pragma unroll
    for (int t = 0; t < 2; t++)
#pragma unroll
        for (int h = 0; h < 2; h++) {
            int co = wt * 16 + t * 16 + (lane >> 2) + h * 8;
            sh1v[t][h] = (co < MID) ? sh1[co] : 0.f;
        }

    int lk = tid >> 4, lc = tid & 15;

    auto issue = [&](int s) {
        uint32_t db = sbB + (s & (STAGES - 1)) * 16384;
#pragma unroll
        for (int it = 0; it < 4; it++) {
            int k = lk + it * 16;
            const __half* gp = srcB + (size_t)(s * 64 + k) * HWP + p0 + lc * 8;
            uint32_t dst = db + k * 256 + ((lc ^ (k & 7)) << 4);
            asm volatile("cp.async.cg.shared.global [%0], [%1], 16;"
                         :: "r"(dst), "l"(gp));
        }
        asm volatile("cp.async.commit_group;");
    };

    issue(0); issue(1); issue(2);

    const int rowl = ((lane >> 3) & 1) * 8 + (lane & 7);
    const int csel = lane >> 4;

    for (int c = 0; c < 4; c++) {
        if (c < 2)       asm volatile("cp.async.wait_group 2;");
        else if (c == 2) asm volatile("cp.async.wait_group 1;");
        else             asm volatile("cp.async.wait_group 0;");
        __syncthreads();

        bool active = (c * 64 < khi) && (c * 64 + 64 > klo);
        if (active) {
            uint32_t stageb = sbB + (c & (STAGES - 1)) * 16384;
#pragma unroll
            for (int h = 0; h < 2; h++) {
                int c32 = c * 2 + h;
                const __half* fb = g_f1 + ((size_t)((c32 * 2) * 8 + wt) * 32 + lane) * 8;
                uint4 af[2][2];
#pragma unroll
                for (int g = 0; g < 2; g++)
#pragma unroll
                    for (int t = 0; t < 2; t++)
                        af[g][t] = *(const uint4*)(fb + ((size_t)g * 8 + t) * 32 * 8);

                uint32_t base = stageb + h * 8192;
#pragma unroll
                for (int g = 0; g < 2; g++) {
                    int row = g * 16 + rowl;
#pragma unroll
                    for (int jp = 0; jp < 4; jp++) {
                        int c16 = nbc + jp * 2 + csel;
                        uint32_t addr = base + row * 256 + ((c16 ^ (row & 7)) << 4);
                        uint32_t b0, b1, b2, b3;
                        asm volatile(
                            "ldmatrix.sync.aligned.m8n8.x4.trans.shared.b16 {%0,%1,%2,%3}, [%4];"
                            : "=r"(b0), "=r"(b1), "=r"(b2), "=r"(b3) : "r"(addr));
                        mma16h(acc[0][jp * 2],     af[g][0], b0, b1);
                        mma16h(acc[1][jp * 2],     af[g][1], b0, b1);
                        mma16h(acc[0][jp * 2 + 1], af[g][0], b2, b3);
                        mma16h(acc[1][jp * 2 + 1], af[g][1], b2, b3);
                    }
                }
            }
        }
        if (c + STAGES - 1 < 4) issue(c + STAGES - 1);
    }

    // epilogue: relu(acc + shift1) -> g_y1h (half2 stores)
#pragma unroll
    for (int t = 0; t < 2; t++) {
#pragma unroll
        for (int h = 0; h < 2; h++) {
            int co = wt * 16 + t * 16 + (lane >> 2) + h * 8;
            if (co >= MID) continue;
            __half* orow = g_y1h + ((size_t)img * MID + co) * HW;
            float bv = sh1v[t][h];
#pragma unroll
            for (int j = 0; j < 8; j++) {
                int p = p0 + nb + j * 8 + 2 * (lane & 3);
                if (p < HW) {
                    *(__half2*)(orow + p) = __floats2half2_rn(
                        fmaxf(acc[t][j][h * 2 + 0] + bv, 0.f),
                        fmaxf(acc[t][j][h * 2 + 1] + bv, 0.f));
                }
            }
        }
    }
}

// ---------------------------------------------------------------------------
// K2: depthwise 3x3 + BN2 + channel shuffle: g_y1h -> g_th (half)
// ---------------------------------------------------------------------------
__global__ __launch_bounds__(448)
void k_dw(const float* __restrict__ w2, const float* __restrict__ s2,
          const float* __restrict__ b2) {
    __shared__ float tile[58][72];
    int m = blockIdx.x;
    int n = blockIdx.y;
    int tx = threadIdx.x, ty = threadIdx.y;
    int tid = ty * 56 + tx;

    if (tid < 36) {
        int r = (tid < 18) ? 0 : 57;
        int c4 = (tid % 18) * 4;
        *(float4*)&tile[r][c4] = make_float4(0.f, 0.f, 0.f, 0.f);
    } else if (tid < 36 + 112) {
        int t = tid - 36;
        int r = 1 + (t >> 1);
        tile[r][(t & 1) ? 64 : 7] = 0.f;
    }

    const __half* src = g_y1h + ((size_t)n * MID + m) * HW;
    if (tid < 392) {
        int r = tid / 7, q = tid - r * 7;
        uint4 v = *(const uint4*)(src + r * 56 + q * 8);
        const __half2* hp = (const __half2*)&v;
        float2 f0 = __half22float2(hp[0]);
        float2 f1 = __half22float2(hp[1]);
        float2 f2 = __half22float2(hp[2]);
        float2 f3 = __half22float2(hp[3]);
        float* d = &tile[r + 1][8 + q * 8];
        *(float4*)d       = make_float4(f0.x, f0.y, f1.x, f1.y);
        *(float4*)(d + 4) = make_float4(f2.x, f2.y, f3.x, f3.y);
    }
    __syncthreads();

    float wv[9];
#pragma unroll
    for (int q = 0; q < 9; q++) wv[q] = __ldg(&w2[m * 9 + q]);
    float sc = __ldg(&s2[m]), sh = __ldg(&b2[m]);

    int cs = (m % 40) * 3 + m / 40;
    __half* dst = g_th + ((size_t)n * 128 + cs) * HWP;

    int r0 = ty * 7;
    int cx = tx + 7;
    float a0 = tile[r0][cx],     a1 = tile[r0][cx + 1],     a2 = tile[r0][cx + 2];
    float e0 = tile[r0 + 1][cx], e1 = tile[r0 + 1][cx + 1], e2 = tile[r0 + 1][cx + 2];
#pragma unroll
    for (int i = 0; i < 7; i++) {
        int row = r0 + i;
        float c0 = tile[row + 2][cx], c1 = tile[row + 2][cx + 1], c2 = tile[row + 2][cx + 2];
        float sum = wv[0] * a0;
        sum = fmaf(wv[1], a1, sum); sum = fmaf(wv[2], a2, sum);
        sum = fmaf(wv[3], e0, sum); sum = fmaf(wv[4], e1, sum);
        sum = fmaf(wv[5], e2, sum); sum = fmaf(wv[6], c0, sum);
        sum = fmaf(wv[7], c1, sum); sum = fmaf(wv[8], c2, sum);
        dst[row * WDIM + tx] = __float2half(fmaf(sc, sum, sh));
        a0 = e0; a1 = e1; a2 = e2;
        e0 = c0; e1 = c1; e2 = c2;
    }
}

// ---------------------------------------------------------------------------
// K3: fused conv3 + relu(bn3) + shortcut + add (R13 body; streaming stores)
// ---------------------------------------------------------------------------
__global__ __launch_bounds__(256)
void k_main_m(const float* __restrict__ sh3, const float* __restrict__ shsc,
              float* __restrict__ out) {
    extern __shared__ __align__(16) char BsRaw[];
    uint32_t sbB = smem_u32(BsRaw);

    int tid = threadIdx.x;
    int wid = tid >> 5, lane = tid & 31;
    int nb = (wid & 1) * 64;
    int nbc = (wid & 1) * 8;
    int wt = (wid >> 1) * 2;

    int mt  = blockIdx.x;
    int p0  = blockIdx.y * 128;
    int img = blockIdx.z;
    int rbase = mt * 128 + wt * 16;

    const int sA = (mt == 3) ? 1 : 0;
    const int nA = (mt == 1 || mt == 2) ? 2 : 1;
    const int nchunk = nA + 4;

    const __half* srcA = g_th + (size_t)img * 128 * HWP;
    const __half* srcB = g_xh + (size_t)img * 256 * HWP;

    float acc[2][8][4];
#pragma unroll
    for (int t = 0; t < 2; t++)
#pragma unroll
        for (int j = 0; j < 8; j++)
#pragma unroll
            for (int q = 0; q < 4; q++) acc[t][j][q] = 0.f;

    float v3[2][2], vsc[2][2];
#pragma unroll
    for (int t = 0; t < 2; t++)
#pragma unroll
        for (int h = 0; h < 2; h++) {
            int co = rbase + t * 16 + (lane >> 2) + h * 8;
            bool ok = co < COUT;
            v3[t][h]  = ok ? sh3[co]  : 0.f;
            vsc[t][h] = ok ? shsc[co] : 0.f;
        }

    int lk = tid >> 4, lc = tid & 15;

    auto issue = [&](int s) {
        const __half* src; int kbase;
        if (s < nA) { src = srcA; kbase = (sA + s) * 64; }
        else        { src = srcB; kbase = (s - nA) * 64; }
        uint32_t db = sbB + (s & (STAGES - 1)) * 16384;
#pragma unroll
        for (int it = 0; it < 4; it++) {
            int k = lk + it * 16;
            const __half* gp = src + (size_t)(kbase + k) * HWP + p0 + lc * 8;
            uint32_t dst = db + k * 256 + ((lc ^ (k & 7)) << 4);
            asm volatile("cp.async.cg.shared.global [%0], [%1], 16;"
                         :: "r"(dst), "l"(gp));
        }
        asm volatile("cp.async.commit_group;");
    };

    issue(0); issue(1); issue(2);

    const int rowl = ((lane >> 3) & 1) * 8 + (lane & 7);
    const int csel = lane >> 4;

    for (int c = 0; c < nchunk; c++) {
        if (c < nchunk - 2)       asm volatile("cp.async.wait_group 2;");
        else if (c == nchunk - 2) asm volatile("cp.async.wait_group 1;");
        else                      asm volatile("cp.async.wait_group 0;");
        __syncthreads();

        uint32_t stageb = sbB + (c & (STAGES - 1)) * 16384;

#pragma unroll
        for (int h = 0; h < 2; h++) {
            int c32 = (c < nA) ? (sA + c) * 2 + h : (c - nA) * 2 + h;
            const __half* fb = (c < nA)
                ? g_fA + ((size_t)((mt * 8  + c32 * 2) * 8 + wt) * 32 + lane) * 8
                : g_fB + ((size_t)((mt * 16 + c32 * 2) * 8 + wt) * 32 + lane) * 8;
            uint4 af[2][2];
#pragma unroll
            for (int g = 0; g < 2; g++)
#pragma unroll
                for (int t = 0; t < 2; t++)
                    af[g][t] = *(const uint4*)(fb + ((size_t)g * 8 + t) * 32 * 8);

            uint32_t base = stageb + h * 8192;
#pragma unroll
            for (int g = 0; g < 2; g++) {
                int row = g * 16 + rowl;
#pragma unroll
                for (int jp = 0; jp < 4; jp++) {
                    int c16 = nbc + jp * 2 + csel;
                    uint32_t addr = base + row * 256 + ((c16 ^ (row & 7)) << 4);
                    uint32_t b0, b1, b2, b3;
                    asm volatile(
                        "ldmatrix.sync.aligned.m8n8.x4.trans.shared.b16 {%0,%1,%2,%3}, [%4];"
                        : "=r"(b0), "=r"(b1), "=r"(b2), "=r"(b3) : "r"(addr));
                    mma16h(acc[0][jp * 2],     af[g][0], b0, b1);
                    mma16h(acc[1][jp * 2],     af[g][1], b0, b1);
                    mma16h(acc[0][jp * 2 + 1], af[g][0], b2, b3);
                    mma16h(acc[1][jp * 2 + 1], af[g][1], b2, b3);
                }
            }
        }

        if (c == nA - 1) {
#pragma unroll
            for (int t = 0; t < 2; t++)
#pragma unroll
                for (int j = 0; j < 8; j++)
#pragma unroll
                    for (int q = 0; q < 4; q++)
                        acc[t][j][q] = fmaxf(acc[t][j][q] + v3[t][q >> 1], 0.f);
        }

        if (c + STAGES - 1 < nchunk) issue(c + STAGES - 1);
    }

    // ---- epilogue: + shift_sc, streaming float2 stores (evict-first) ----
#pragma unroll
    for (int t = 0; t < 2; t++) {
#pragma unroll
        for (int h = 0; h < 2; h++) {
            int co = rbase + t * 16 + (lane >> 2) + h * 8;
            if (co >= COUT) continue;
            float* orow = out + ((size_t)img * COUT + co) * HW;
            float bv = vsc[t][h];
#pragma unroll
            for (int j = 0; j < 8; j++) {
                int p = p0 + nb + j * 8 + 2 * (lane & 3);
                if (p < HW) {
                    st_cs_f2(orow + p,
                             acc[t][j][h * 2 + 0] + bv,
                             acc[t][j][h * 2 + 1] + bv);
                }
            }
        }
    }
}

// ---------------------------------------------------------------------------
extern "C" void kernel_launch(void* const* d_in, const int* in_sizes, int n_in,
                              void* d_out, int out_size) {
    const float* x   = (const float*)d_in[0];
    const float* w1  = (const float*)d_in[1];
    const float* s1  = (const float*)d_in[2];
    const float* b1  = (const float*)d_in[3];
    const float* w2  = (const float*)d_in[4];
    const float* s2  = (const float*)d_in[5];
    const float* b2  = (const float*)d_in[6];
    const float* w3  = (const float*)d_in[7];
    const float* s3  = (const float*)d_in[8];
    const float* b3  = (const float*)d_in[9];
    const float* wsc = (const float*)d_in[10];
    const float* ssc = (const float*)d_in[11];
    const float* bsc = (const float*)d_in[12];
    float* out = (float*)d_out;

    static int smem_set = 0;
    if (!smem_set) {
        cudaFuncSetAttribute(k_main_m, cudaFuncAttributeMaxDynamicSharedMemorySize,
                             STAGES * 16384);
        cudaFuncSetAttribute(k_conv1_t, cudaFuncAttributeMaxDynamicSharedMemorySize,
                             STAGES * 16384);
        smem_set = 1;
    }

    int ncvt_blocks = (NB * CIN * (HW / 4) + 255) / 256;   // 23520
    k_prep<<<NFB + ncvt_blocks, 256>>>(w3, s3, wsc, ssc, w1, s1, x);
    k_conv1_t<<<dim3(25, NB), 256, STAGES * 16384>>>(b1);
    k_dw<<<dim3(MID, NB), dim3(56, 8)>>>(w2, s2, b2);
    k_main_m<<<dim3(4, 25, NB), 256, STAGES * 16384>>>(b3, bsc, out);
}